// round 10
// baseline (speedup 1.0000x reference)
#include <cuda_runtime.h>
#include <stdint.h>

#define NUM_BUCKETS 4000000u
#define NUM_FIELDS  63
#define NUM_SEG     64
#define SEQ         500
#define BATCH       16384
#define NT          64        // threads per CTA (2 warps); priv column per thread

// 0 = indices/fields are int32, 1 = int64. Set by probe kernel each launch.
__device__ int g_is64;

// Detect int32 vs int64 element width of the `indexes` buffer.
// For int64 data (positive, < 2^32), every odd 32-bit word is zero.
// For int32 data uniform in [0, 1e8), an odd word is zero with p ~= 1e-8.
// Reads first 8192 words = 32 KB, safely inside either buffer size.
__global__ void probe_dtype_kernel(const unsigned int* __restrict__ w) {
    __shared__ unsigned int s_any;
    if (threadIdx.x == 0) s_any = 0u;
    __syncthreads();
    unsigned int acc = 0u;
    for (int i = 2 * threadIdx.x + 1; i < 8192; i += 2 * blockDim.x)
        acc |= w[i];
    if (acc) atomicOr(&s_any, 1u);
    __syncthreads();
    if (threadIdx.x == 0) g_is64 = (s_any == 0u) ? 1 : 0;
}

// One CTA (64 threads) per batch row. NO shared atomics: each thread owns a
// private 64-float column priv[f*NT + t]; bank index = t mod 32, so both the
// accumulation and the rotated reduction are 100% bank-conflict-free.
__global__ __launch_bounds__(NT) void wide_pool_kernel(
    const void* __restrict__ idx_raw,
    const void* __restrict__ fld_raw,
    const float* __restrict__ values,
    const float* __restrict__ table,
    float* __restrict__ out)
{
    __shared__ float priv[NUM_SEG * NT];   // 16 KB
    const int b = blockIdx.x;
    const int t = threadIdx.x;

    // Zero private accumulators (vectorized: 1024 float4 / 64 threads = 16 each)
    {
        float4 z = make_float4(0.f, 0.f, 0.f, 0.f);
        float4* p4 = (float4*)priv;
        #pragma unroll
        for (int i = 0; i < (NUM_SEG * NT / 4) / NT; i++)
            p4[t + i * NT] = z;
    }
    __syncthreads();

    const int is64 = g_is64;
    const long rowbase = (long)b * SEQ;

    // 125 vec4 groups per row; thread t handles group t and (t+64 if < 125).
    #pragma unroll
    for (int g = 0; g < 2; g++) {
        const int v = t + g * NT;
        if (v < SEQ / 4) {
            const long base = rowbase + (long)v * 4;   // 16B aligned

            unsigned int i0, i1, i2, i3, f0, f1, f2, f3;
            if (is64) {
                const ulonglong2* __restrict__ ip = (const ulonglong2*)idx_raw;
                const ulonglong2* __restrict__ fp = (const ulonglong2*)fld_raw;
                const long h = base >> 1;
                ulonglong2 ia = __ldcs(&ip[h]);
                ulonglong2 ib = __ldcs(&ip[h + 1]);
                ulonglong2 fa = __ldcs(&fp[h]);
                ulonglong2 fb = __ldcs(&fp[h + 1]);
                i0 = (unsigned int)ia.x; i1 = (unsigned int)ia.y;
                i2 = (unsigned int)ib.x; i3 = (unsigned int)ib.y;
                f0 = (unsigned int)fa.x; f1 = (unsigned int)fa.y;
                f2 = (unsigned int)fb.x; f3 = (unsigned int)fb.y;
            } else {
                const uint4* __restrict__ ip = (const uint4*)idx_raw;
                const uint4* __restrict__ fp = (const uint4*)fld_raw;
                const long q = base >> 2;
                uint4 ia = __ldcs(&ip[q]);
                uint4 fa = __ldcs(&fp[q]);
                i0 = ia.x; i1 = ia.y; i2 = ia.z; i3 = ia.w;
                f0 = fa.x; f1 = fa.y; f2 = fa.z; f3 = fa.w;
            }

            const float4 vv = __ldcs((const float4*)(values + base));

            // Batch the 4 random gathers (MLP=4), L2-only.
            const float e0 = __ldcg(table + (i0 % NUM_BUCKETS));
            const float e1 = __ldcg(table + (i1 % NUM_BUCKETS));
            const float e2 = __ldcg(table + (i2 % NUM_BUCKETS));
            const float e3 = __ldcg(table + (i3 % NUM_BUCKETS));

            // Conflict-free private accumulation (no atomics).
            priv[(f0 & (NUM_SEG - 1)) * NT + t] += e0 * vv.x;
            priv[(f1 & (NUM_SEG - 1)) * NT + t] += e1 * vv.y;
            priv[(f2 & (NUM_SEG - 1)) * NT + t] += e2 * vv.z;
            priv[(f3 & (NUM_SEG - 1)) * NT + t] += e3 * vv.w;
        }
    }

    __syncthreads();

    // Thread t reduces segment t. Rotated column order (j+t)&63 keeps every
    // LDS conflict-free. 4 partial sums break the FADD dependency chain.
    {
        float s0 = 0.f, s1 = 0.f, s2 = 0.f, s3 = 0.f;
        const float* row = priv + t * NT;
        #pragma unroll
        for (int j = 0; j < NT; j += 4) {
            s0 += row[(j + 0 + t) & (NT - 1)];
            s1 += row[(j + 1 + t) & (NT - 1)];
            s2 += row[(j + 2 + t) & (NT - 1)];
            s3 += row[(j + 3 + t) & (NT - 1)];
        }
        const float sum = (s0 + s1) + (s2 + s3);
        // Drop segment 0 (padding field); fields 1..63 -> out[b, f-1].
        if (t >= 1)
            out[(long)b * NUM_FIELDS + (t - 1)] = sum;
    }
}

extern "C" void kernel_launch(void* const* d_in, const int* in_sizes, int n_in,
                              void* d_out, int out_size) {
    // metadata order: indexes, fields, values, emb_table
    const void*  d_idx   = d_in[0];
    const void*  d_fld   = d_in[1];
    const float* d_val   = (const float*)d_in[2];
    const float* d_table = (const float*)d_in[3];
    float*       out     = (float*)d_out;

    probe_dtype_kernel<<<1, 256>>>((const unsigned int*)d_idx);
    wide_pool_kernel<<<BATCH, NT>>>(d_idx, d_fld, d_val, d_table, out);
}

// round 11
// speedup vs baseline: 1.0851x; 1.0851x over previous
#include <cuda_runtime.h>
#include <stdint.h>

#define NUM_BUCKETS 4000000u
#define NUM_FIELDS  63
#define NUM_SEG     64
#define SEQ         500
#define BATCH       16384
#define NT          64          // columns (threads) per row-group
#define RPC         2           // rows per CTA
#define THREADS     (NT * RPC)  // 128

// 0 = indices/fields are int32, 1 = int64. Set by probe kernel each launch.
__device__ int g_is64;

// Detect int32 vs int64 element width of the `indexes` buffer.
// For int64 data (positive, < 2^32), every odd 32-bit word is zero.
// For int32 data uniform in [0, 1e8), an odd word is zero with p ~= 1e-8.
// Reads first 8192 words = 32 KB, safely inside either buffer size.
__global__ void probe_dtype_kernel(const unsigned int* __restrict__ w) {
    __shared__ unsigned int s_any;
    if (threadIdx.x == 0) s_any = 0u;
    __syncthreads();
    unsigned int acc = 0u;
    for (int i = 2 * threadIdx.x + 1; i < 8192; i += 2 * blockDim.x)
        acc |= w[i];
    if (acc) atomicOr(&s_any, 1u);
    __syncthreads();
    if (threadIdx.x == 0) g_is64 = (s_any == 0u) ? 1 : 0;
}

// 2 rows per CTA (128 threads). Each row-group of 64 threads privatizes:
// priv[f*64 + t] (stride 64 == 0 mod 32 banks -> column==thread is perfectly
// bank-conflict-free for ANY field pattern). No atomics anywhere.
// Reduction: coalesced float4 reads + shfl-xor tree (2 segments per warp-op).
__global__ __launch_bounds__(THREADS) void wide_pool_kernel(
    const void* __restrict__ idx_raw,
    const void* __restrict__ fld_raw,
    const float* __restrict__ values,
    const float* __restrict__ table,
    float* __restrict__ out)
{
    __shared__ float priv[RPC * NUM_SEG * NT];   // 32 KB
    const int tid = threadIdx.x;
    const int rg  = tid >> 6;          // row-group 0/1
    const int t   = tid & (NT - 1);    // column within group

    // ---- zero accumulators: 2048 float4 / 128 threads = 16 each, coalesced
    {
        float4 z = make_float4(0.f, 0.f, 0.f, 0.f);
        float4* p4 = (float4*)priv;
        #pragma unroll
        for (int i = 0; i < (RPC * NUM_SEG * NT / 4) / THREADS; i++)
            p4[tid + i * THREADS] = z;
    }
    __syncthreads();

    const int is64 = g_is64;
    const long row = (long)blockIdx.x * RPC + rg;
    const long rowbase = row * SEQ;
    float* __restrict__ P = priv + rg * (NUM_SEG * NT);

    // ---- accumulate: 125 vec4 groups per row; thread t takes v = t, t+64
    #pragma unroll
    for (int g = 0; g < 2; g++) {
        const int v = t + g * NT;
        if (v < SEQ / 4) {
            const long base = rowbase + (long)v * 4;   // 16B aligned

            unsigned int i0, i1, i2, i3, f0, f1, f2, f3;
            if (is64) {
                const ulonglong2* __restrict__ ip = (const ulonglong2*)idx_raw;
                const ulonglong2* __restrict__ fp = (const ulonglong2*)fld_raw;
                const long h = base >> 1;
                ulonglong2 ia = __ldcs(&ip[h]);
                ulonglong2 ib = __ldcs(&ip[h + 1]);
                ulonglong2 fa = __ldcs(&fp[h]);
                ulonglong2 fb = __ldcs(&fp[h + 1]);
                i0 = (unsigned int)ia.x; i1 = (unsigned int)ia.y;
                i2 = (unsigned int)ib.x; i3 = (unsigned int)ib.y;
                f0 = (unsigned int)fa.x; f1 = (unsigned int)fa.y;
                f2 = (unsigned int)fb.x; f3 = (unsigned int)fb.y;
            } else {
                const uint4* __restrict__ ip = (const uint4*)idx_raw;
                const uint4* __restrict__ fp = (const uint4*)fld_raw;
                const long q = base >> 2;
                uint4 ia = __ldcs(&ip[q]);
                uint4 fa = __ldcs(&fp[q]);
                i0 = ia.x; i1 = ia.y; i2 = ia.z; i3 = ia.w;
                f0 = fa.x; f1 = fa.y; f2 = fa.z; f3 = fa.w;
            }

            const float4 vv = __ldcs((const float4*)(values + base));

            // Batch the 4 random gathers (MLP=4), L2-only.
            const float e0 = __ldcg(table + (i0 % NUM_BUCKETS));
            const float e1 = __ldcg(table + (i1 % NUM_BUCKETS));
            const float e2 = __ldcg(table + (i2 % NUM_BUCKETS));
            const float e3 = __ldcg(table + (i3 % NUM_BUCKETS));

            // Conflict-free private accumulation (no atomics).
            P[(f0 & (NUM_SEG - 1)) * NT + t] += e0 * vv.x;
            P[(f1 & (NUM_SEG - 1)) * NT + t] += e1 * vv.y;
            P[(f2 & (NUM_SEG - 1)) * NT + t] += e2 * vv.z;
            P[(f3 & (NUM_SEG - 1)) * NT + t] += e3 * vv.w;
        }
    }

    __syncthreads();

    // ---- reduce: warp w handles 32 segments (half h) of row-group (w>>1).
    // Each warp-op: 32 consecutive float4 (512B coalesced, conflict-free)
    // = 128 floats = 2 full segments; shfl-xor over 16-lane halves.
    {
        const int w    = tid >> 5;
        const int lane = tid & 31;
        const int rr   = w >> 1;
        const int h    = w & 1;
        const float4* __restrict__ q4 =
            (const float4*)(priv + rr * (NUM_SEG * NT)) + h * (32 * NT / 4);
        const long orow = (long)blockIdx.x * RPC + rr;

        #pragma unroll
        for (int j = 0; j < 16; j++) {
            float4 v = q4[j * 32 + lane];
            float s = (v.x + v.y) + (v.z + v.w);
            s += __shfl_xor_sync(0xffffffffu, s, 1);
            s += __shfl_xor_sync(0xffffffffu, s, 2);
            s += __shfl_xor_sync(0xffffffffu, s, 4);
            s += __shfl_xor_sync(0xffffffffu, s, 8);
            // lanes 0..15 -> segment 2j, lanes 16..31 -> segment 2j+1
            const int f = h * 32 + 2 * j + (lane >> 4);
            if ((lane & 15) == 0 && f > 0)
                out[orow * NUM_FIELDS + (f - 1)] = s;   // drop padding field 0
        }
    }
}

extern "C" void kernel_launch(void* const* d_in, const int* in_sizes, int n_in,
                              void* d_out, int out_size) {
    // metadata order: indexes, fields, values, emb_table
    const void*  d_idx   = d_in[0];
    const void*  d_fld   = d_in[1];
    const float* d_val   = (const float*)d_in[2];
    const float* d_table = (const float*)d_in[3];
    float*       out     = (float*)d_out;

    probe_dtype_kernel<<<1, 256>>>((const unsigned int*)d_idx);
    wide_pool_kernel<<<BATCH / RPC, THREADS>>>(d_idx, d_fld, d_val, d_table, out);
}

// round 12
// speedup vs baseline: 1.9174x; 1.7671x over previous
#include <cuda_runtime.h>
#include <stdint.h>

#define NUM_BUCKETS 4000000u
#define NUM_FIELDS  63
#define NUM_SEG     64
#define SEQ         500
#define BATCH       16384
#define GROUPS      (BATCH * SEQ / 4)   // 2,048,000 vec4 groups
#define GPR         (SEQ / 4)           // 125 groups per row (500 % 4 == 0)
#define OUT_ELEMS   (BATCH * NUM_FIELDS)

// 0 = indices/fields are int32, 1 = int64. Set by probe kernel each launch.
__device__ int g_is64;

// Detect int32 vs int64 element width of the `indexes` buffer.
// For int64 data (positive, < 2^32), every odd 32-bit word is zero.
// For int32 data uniform in [0, 1e8), an odd word is zero with p ~= 1e-8.
// Reads first 8192 words = 32 KB, safely inside either buffer size.
__global__ void probe_dtype_kernel(const unsigned int* __restrict__ w) {
    __shared__ unsigned int s_any;
    if (threadIdx.x == 0) s_any = 0u;
    __syncthreads();
    unsigned int acc = 0u;
    for (int i = 2 * threadIdx.x + 1; i < 8192; i += 2 * blockDim.x)
        acc |= w[i];
    if (acc) atomicOr(&s_any, 1u);
    __syncthreads();
    if (threadIdx.x == 0) g_is64 = (s_any == 0u) ? 1 : 0;
}

// Zero the (poisoned) output: 1,032,192 floats = 258,048 float4, grid-stride.
__global__ __launch_bounds__(256) void zero_out_kernel(float4* __restrict__ o4) {
    const float4 z = make_float4(0.f, 0.f, 0.f, 0.f);
    const int stride = gridDim.x * blockDim.x;
    for (int i = blockIdx.x * blockDim.x + threadIdx.x; i < OUT_ELEMS / 4; i += stride)
        o4[i] = z;
}

// One vec4 group (4 elements, same row) per thread. No shared memory, no
// block reduction: contributions go straight to the 4MB (L2-resident) output
// via no-return global atomics (REDG), executed by the LTS atomic ALUs.
// This keeps the SM-side L1tex pipe carrying ONLY the random table gathers.
__global__ __launch_bounds__(256) void wide_scatter_kernel(
    const void* __restrict__ idx_raw,
    const void* __restrict__ fld_raw,
    const float* __restrict__ values,
    const float* __restrict__ table,
    float* __restrict__ out)
{
    const int g = blockIdx.x * blockDim.x + threadIdx.x;   // group id < GROUPS
    const unsigned row = (unsigned)g / GPR;                // groups never straddle rows
    const long base = (long)g * 4;                         // 16B-aligned element base

    unsigned int i0, i1, i2, i3, f0, f1, f2, f3;
    if (g_is64) {
        const ulonglong2* __restrict__ ip = (const ulonglong2*)idx_raw;
        const ulonglong2* __restrict__ fp = (const ulonglong2*)fld_raw;
        const long h = base >> 1;
        ulonglong2 ia = __ldcs(&ip[h]);
        ulonglong2 ib = __ldcs(&ip[h + 1]);
        ulonglong2 fa = __ldcs(&fp[h]);
        ulonglong2 fb = __ldcs(&fp[h + 1]);
        i0 = (unsigned int)ia.x; i1 = (unsigned int)ia.y;
        i2 = (unsigned int)ib.x; i3 = (unsigned int)ib.y;
        f0 = (unsigned int)fa.x; f1 = (unsigned int)fa.y;
        f2 = (unsigned int)fb.x; f3 = (unsigned int)fb.y;
    } else {
        const uint4* __restrict__ ip = (const uint4*)idx_raw;
        const uint4* __restrict__ fp = (const uint4*)fld_raw;
        const long q = base >> 2;
        uint4 ia = __ldcs(&ip[q]);
        uint4 fa = __ldcs(&fp[q]);
        i0 = ia.x; i1 = ia.y; i2 = ia.z; i3 = ia.w;
        f0 = fa.x; f1 = fa.y; f2 = fa.z; f3 = fa.w;
    }

    const float4 vv = __ldcs((const float4*)(values + base));

    // Batch the 4 random gathers (MLP=4), L2-only (table ~1% L1-resident).
    const float e0 = __ldcg(table + (i0 % NUM_BUCKETS));
    const float e1 = __ldcg(table + (i1 % NUM_BUCKETS));
    const float e2 = __ldcg(table + (i2 % NUM_BUCKETS));
    const float e3 = __ldcg(table + (i3 % NUM_BUCKETS));

    // Scatter: drop padding field 0; field f -> out[row, f-1].
    float* __restrict__ orow = out + (long)row * NUM_FIELDS - 1;
    if (f0) atomicAdd(orow + (f0 & (NUM_SEG - 1)), e0 * vv.x);  // no-return -> REDG
    if (f1) atomicAdd(orow + (f1 & (NUM_SEG - 1)), e1 * vv.y);
    if (f2) atomicAdd(orow + (f2 & (NUM_SEG - 1)), e2 * vv.z);
    if (f3) atomicAdd(orow + (f3 & (NUM_SEG - 1)), e3 * vv.w);
}

extern "C" void kernel_launch(void* const* d_in, const int* in_sizes, int n_in,
                              void* d_out, int out_size) {
    // metadata order: indexes, fields, values, emb_table
    const void*  d_idx   = d_in[0];
    const void*  d_fld   = d_in[1];
    const float* d_val   = (const float*)d_in[2];
    const float* d_table = (const float*)d_in[3];
    float*       out     = (float*)d_out;

    probe_dtype_kernel<<<1, 256>>>((const unsigned int*)d_idx);
    zero_out_kernel<<<256, 256>>>((float4*)out);
    wide_scatter_kernel<<<GROUPS / 256, 256>>>(d_idx, d_fld, d_val, d_table, out);
}

// round 13
// speedup vs baseline: 1.9810x; 1.0332x over previous
#include <cuda_runtime.h>
#include <stdint.h>

#define NUM_BUCKETS 4000000u
#define NUM_FIELDS  63
#define NUM_SEG     64
#define SEQ         500
#define BATCH       16384
#define GROUPS      (BATCH * SEQ / 4)   // 2,048,000 vec4 groups
#define GPR         (SEQ / 4)           // 125 groups per row (500 % 4 == 0)
#define OUT_ELEMS   (BATCH * NUM_FIELDS)

// Zero the (poisoned) output: 1,032,192 floats = 258,048 float4.
// Grid is sized so each thread writes exactly one float4.
__global__ __launch_bounds__(256) void zero_out_kernel(float4* __restrict__ o4) {
    const int i = blockIdx.x * blockDim.x + threadIdx.x;
    if (i < OUT_ELEMS / 4)
        o4[i] = make_float4(0.f, 0.f, 0.f, 0.f);
}

// One vec4 group (4 elements, same row) per thread. No shared memory, no
// block reduction: contributions go straight to the 4MB (L2-resident) output
// via no-return global atomics (REDG), executed by the LTS atomic ALUs.
// dtype (int32 vs int64) is detected inline per warp: lane L reads odd word
// 2L+1 of the indexes buffer (first 256B -> broadcast L1/L2 hit); for int64
// data (ids < 2^32) all odd words are zero, for int32 data (uniform < 1e8)
// P(all 32 zero) ~ 1e-256. One LDG + one ballot, no separate probe kernel.
__global__ __launch_bounds__(256) void wide_scatter_kernel(
    const void* __restrict__ idx_raw,
    const void* __restrict__ fld_raw,
    const float* __restrict__ values,
    const float* __restrict__ table,
    float* __restrict__ out)
{
    const int lane = threadIdx.x & 31;
    const unsigned probe = __ldg((const unsigned int*)idx_raw + 2 * lane + 1);
    const bool is64 = (__ballot_sync(0xffffffffu, probe != 0u) == 0u);

    const int g = blockIdx.x * blockDim.x + threadIdx.x;   // group id < GROUPS
    const unsigned row = (unsigned)g / GPR;                // groups never straddle rows
    const long base = (long)g * 4;                         // 16B-aligned element base

    unsigned int i0, i1, i2, i3, f0, f1, f2, f3;
    if (is64) {
        const ulonglong2* __restrict__ ip = (const ulonglong2*)idx_raw;
        const ulonglong2* __restrict__ fp = (const ulonglong2*)fld_raw;
        const long h = base >> 1;
        ulonglong2 ia = __ldcs(&ip[h]);
        ulonglong2 ib = __ldcs(&ip[h + 1]);
        ulonglong2 fa = __ldcs(&fp[h]);
        ulonglong2 fb = __ldcs(&fp[h + 1]);
        i0 = (unsigned int)ia.x; i1 = (unsigned int)ia.y;
        i2 = (unsigned int)ib.x; i3 = (unsigned int)ib.y;
        f0 = (unsigned int)fa.x; f1 = (unsigned int)fa.y;
        f2 = (unsigned int)fb.x; f3 = (unsigned int)fb.y;
    } else {
        const uint4* __restrict__ ip = (const uint4*)idx_raw;
        const uint4* __restrict__ fp = (const uint4*)fld_raw;
        const long q = base >> 2;
        uint4 ia = __ldcs(&ip[q]);
        uint4 fa = __ldcs(&fp[q]);
        i0 = ia.x; i1 = ia.y; i2 = ia.z; i3 = ia.w;
        f0 = fa.x; f1 = fa.y; f2 = fa.z; f3 = fa.w;
    }

    const float4 vv = __ldcs((const float4*)(values + base));

    // Batch the 4 random gathers (MLP=4), L2-only (table ~1% L1-resident).
    const float e0 = __ldcg(table + (i0 % NUM_BUCKETS));
    const float e1 = __ldcg(table + (i1 % NUM_BUCKETS));
    const float e2 = __ldcg(table + (i2 % NUM_BUCKETS));
    const float e3 = __ldcg(table + (i3 % NUM_BUCKETS));

    // Scatter: drop padding field 0; field f -> out[row, f-1].
    float* __restrict__ orow = out + (long)row * NUM_FIELDS - 1;
    if (f0) atomicAdd(orow + (f0 & (NUM_SEG - 1)), e0 * vv.x);  // no-return -> REDG
    if (f1) atomicAdd(orow + (f1 & (NUM_SEG - 1)), e1 * vv.y);
    if (f2) atomicAdd(orow + (f2 & (NUM_SEG - 1)), e2 * vv.z);
    if (f3) atomicAdd(orow + (f3 & (NUM_SEG - 1)), e3 * vv.w);
}

extern "C" void kernel_launch(void* const* d_in, const int* in_sizes, int n_in,
                              void* d_out, int out_size) {
    // metadata order: indexes, fields, values, emb_table
    const void*  d_idx   = d_in[0];
    const void*  d_fld   = d_in[1];
    const float* d_val   = (const float*)d_in[2];
    const float* d_table = (const float*)d_in[3];
    float*       out     = (float*)d_out;

    zero_out_kernel<<<(OUT_ELEMS / 4 + 255) / 256, 256>>>((float4*)out);
    wide_scatter_kernel<<<GROUPS / 256, 256>>>(d_idx, d_fld, d_val, d_table, out);
}

// round 14
// speedup vs baseline: 2.0693x; 1.0446x over previous
#include <cuda_runtime.h>
#include <stdint.h>

#define NUM_BUCKETS 4000000u
#define NUM_FIELDS  63
#define NUM_SEG     64
#define SEQ         500
#define BATCH       16384
#define GROUPS      (BATCH * SEQ / 4)   // 2,048,000 vec4 groups
#define GPR         (SEQ / 4)           // 125 groups per row (500 % 4 == 0)
#define HALF        (GROUPS / 2)        // 1,024,000 = 4000 CTAs x 256
#define OUT_ELEMS   (BATCH * NUM_FIELDS)

// Zero the (poisoned) output: 1,032,192 floats = 258,048 float4.
__global__ __launch_bounds__(256) void zero_out_kernel(float4* __restrict__ o4) {
    const int i = blockIdx.x * blockDim.x + threadIdx.x;
    if (i < OUT_ELEMS / 4)
        o4[i] = make_float4(0.f, 0.f, 0.f, 0.f);
}

// Two vec4 groups (8 elements) per thread: g and g+HALF. All 8 random table
// gathers are issued back-to-back (MLP=8/thread) before any consumption, to
// keep the L1tex wavefront queue full (R13 showed it at 73% with MLP=4).
// Scatter goes straight to the 4MB L2-resident output via no-return global
// atomics (REDG) executed in the LTS atomic ALUs — no smem, no block reduce.
// dtype (int32 vs int64) detected inline per warp: lane L reads odd word 2L+1
// of indexes (first 256B, broadcast hit); int64 data (ids < 2^32) has all odd
// words zero; for int32 uniform < 1e8, P(all 32 zero) ~ 1e-256.
__global__ __launch_bounds__(256) void wide_scatter_kernel(
    const void* __restrict__ idx_raw,
    const void* __restrict__ fld_raw,
    const float* __restrict__ values,
    const float* __restrict__ table,
    float* __restrict__ out)
{
    const int lane = threadIdx.x & 31;
    const unsigned probe = __ldg((const unsigned int*)idx_raw + 2 * lane + 1);
    const bool is64 = (__ballot_sync(0xffffffffu, probe != 0u) == 0u);

    const int g0 = blockIdx.x * blockDim.x + threadIdx.x;  // < HALF
    const int g1 = g0 + HALF;
    const unsigned row0 = (unsigned)g0 / GPR;
    const unsigned row1 = (unsigned)g1 / GPR;
    const long base0 = (long)g0 * 4;                       // 16B-aligned
    const long base1 = (long)g1 * 4;

    unsigned ia[8], fa[8];
    if (is64) {
        const ulonglong2* __restrict__ ip = (const ulonglong2*)idx_raw;
        const ulonglong2* __restrict__ fp = (const ulonglong2*)fld_raw;
        const long h0 = base0 >> 1, h1 = base1 >> 1;
        ulonglong2 a0 = __ldcs(&ip[h0]),     a1 = __ldcs(&ip[h0 + 1]);
        ulonglong2 a2 = __ldcs(&ip[h1]),     a3 = __ldcs(&ip[h1 + 1]);
        ulonglong2 b0 = __ldcs(&fp[h0]),     b1 = __ldcs(&fp[h0 + 1]);
        ulonglong2 b2 = __ldcs(&fp[h1]),     b3 = __ldcs(&fp[h1 + 1]);
        ia[0] = (unsigned)a0.x; ia[1] = (unsigned)a0.y;
        ia[2] = (unsigned)a1.x; ia[3] = (unsigned)a1.y;
        ia[4] = (unsigned)a2.x; ia[5] = (unsigned)a2.y;
        ia[6] = (unsigned)a3.x; ia[7] = (unsigned)a3.y;
        fa[0] = (unsigned)b0.x; fa[1] = (unsigned)b0.y;
        fa[2] = (unsigned)b1.x; fa[3] = (unsigned)b1.y;
        fa[4] = (unsigned)b2.x; fa[5] = (unsigned)b2.y;
        fa[6] = (unsigned)b3.x; fa[7] = (unsigned)b3.y;
    } else {
        const uint4* __restrict__ ip = (const uint4*)idx_raw;
        const uint4* __restrict__ fp = (const uint4*)fld_raw;
        const long q0 = base0 >> 2, q1 = base1 >> 2;
        uint4 a0 = __ldcs(&ip[q0]), a1 = __ldcs(&ip[q1]);
        uint4 b0 = __ldcs(&fp[q0]), b1 = __ldcs(&fp[q1]);
        ia[0] = a0.x; ia[1] = a0.y; ia[2] = a0.z; ia[3] = a0.w;
        ia[4] = a1.x; ia[5] = a1.y; ia[6] = a1.z; ia[7] = a1.w;
        fa[0] = b0.x; fa[1] = b0.y; fa[2] = b0.z; fa[3] = b0.w;
        fa[4] = b1.x; fa[5] = b1.y; fa[6] = b1.z; fa[7] = b1.w;
    }

    const float4 v0 = __ldcs((const float4*)(values + base0));
    const float4 v1 = __ldcs((const float4*)(values + base1));

    // 8 random gathers batched (L2-only: table has ~1% L1 residency).
    float e[8];
    #pragma unroll
    for (int k = 0; k < 8; k++)
        e[k] = __ldcg(table + (ia[k] % NUM_BUCKETS));

    const float vv[8] = { v0.x, v0.y, v0.z, v0.w, v1.x, v1.y, v1.z, v1.w };

    // Scatter: drop padding field 0; field f -> out[row, f-1].
    float* __restrict__ o0 = out + (long)row0 * NUM_FIELDS - 1;
    float* __restrict__ o1 = out + (long)row1 * NUM_FIELDS - 1;
    #pragma unroll
    for (int k = 0; k < 4; k++) {
        const unsigned f = fa[k] & (NUM_SEG - 1);
        if (f) atomicAdd(o0 + f, e[k] * vv[k]);            // no-return -> REDG
    }
    #pragma unroll
    for (int k = 4; k < 8; k++) {
        const unsigned f = fa[k] & (NUM_SEG - 1);
        if (f) atomicAdd(o1 + f, e[k] * vv[k]);
    }
}

extern "C" void kernel_launch(void* const* d_in, const int* in_sizes, int n_in,
                              void* d_out, int out_size) {
    // metadata order: indexes, fields, values, emb_table
    const void*  d_idx   = d_in[0];
    const void*  d_fld   = d_in[1];
    const float* d_val   = (const float*)d_in[2];
    const float* d_table = (const float*)d_in[3];
    float*       out     = (float*)d_out;

    zero_out_kernel<<<(OUT_ELEMS / 4 + 255) / 256, 256>>>((float4*)out);
    wide_scatter_kernel<<<HALF / 256, 256>>>(d_idx, d_fld, d_val, d_table, out);
}